// round 2
// baseline (speedup 1.0000x reference)
#include <cuda_runtime.h>
#include <cuda_bf16.h>
#include <math.h>

#define NN 100000
#define NE 1000000
#define D  64

// ---------------- scratch (__device__ globals: the sanctioned scratch) ------
__device__ int   g_deg[NN];
__device__ int   g_cur[NN];
__device__ int   g_off[NN];
__device__ int   g_adj[NE];
__device__ float g_mean[NN * D];
__device__ float g_h[NN * D];
__device__ int   g_bsum[128];
__device__ int   g_boff[128];
__device__ int   g_is64;

#define SCAN_B 1024
#define SCAN_NB ((NN + SCAN_B - 1) / SCAN_B)   // 98

// ---------------- edge dtype detection --------------------------------------
// JAX may emit edge_index as int32 (x64 disabled) or int64. Detect on device:
// if the buffer really is int64, every value lies in [0, NN). If it is int32
// read as int64, the high word is the next edge (almost surely nonzero).
__global__ void k_detect(const long long* __restrict__ ei) {
    __shared__ int bad;
    if (threadIdx.x == 0) bad = 0;
    __syncthreads();
    for (int i = threadIdx.x; i < 2048; i += blockDim.x) {
        long long v = ei[i];
        if (v < 0 || v >= NN) bad = 1;
    }
    __syncthreads();
    if (threadIdx.x == 0) g_is64 = bad ? 0 : 1;
}

__device__ __forceinline__ int edge_at(const void* ei, int idx) {
    if (g_is64) return (int)((const long long*)ei)[idx];
    return ((const int*)ei)[idx];
}

// ---------------- CSR build --------------------------------------------------
__global__ void k_zero(void) {
    int i = blockIdx.x * blockDim.x + threadIdx.x;
    if (i < NN) { g_deg[i] = 0; g_cur[i] = 0; }
}

__global__ void k_hist(const void* __restrict__ ei) {
    int e = blockIdx.x * blockDim.x + threadIdx.x;
    if (e < NE) {
        int dst = edge_at(ei, NE + e);
        if ((unsigned)dst < NN) atomicAdd(&g_deg[dst], 1);
    }
}

__global__ void k_scan1(void) {
    __shared__ int s[SCAN_B];
    int i = blockIdx.x * SCAN_B + threadIdx.x;
    int v = (i < NN) ? g_deg[i] : 0;
    s[threadIdx.x] = v;
    __syncthreads();
    for (int st = 1; st < SCAN_B; st <<= 1) {
        int t = 0;
        if ((int)threadIdx.x >= st) t = s[threadIdx.x - st];
        __syncthreads();
        s[threadIdx.x] += t;
        __syncthreads();
    }
    if (i < NN) g_off[i] = s[threadIdx.x] - v;  // exclusive within chunk
    if (threadIdx.x == SCAN_B - 1) g_bsum[blockIdx.x] = s[SCAN_B - 1];
}

__global__ void k_scan2(void) {
    if (threadIdx.x == 0 && blockIdx.x == 0) {
        int acc = 0;
        for (int b = 0; b < SCAN_NB; b++) {
            int t = g_bsum[b];
            g_boff[b] = acc;
            acc += t;
        }
    }
}

__global__ void k_scan3(void) {
    int i = blockIdx.x * SCAN_B + threadIdx.x;
    if (i < NN) g_off[i] += g_boff[blockIdx.x];
}

__global__ void k_fill(const void* __restrict__ ei) {
    int e = blockIdx.x * blockDim.x + threadIdx.x;
    if (e < NE) {
        int src = edge_at(ei, e);
        int dst = edge_at(ei, NE + e);
        if ((unsigned)dst < NN && (unsigned)src < NN) {
            int p = g_off[dst] + atomicAdd(&g_cur[dst], 1);
            g_adj[p] = src;
        }
    }
}

// ---------------- mean aggregation: one warp per node -----------------------
__global__ void k_agg(const float* __restrict__ feat, float* __restrict__ outm) {
    int warp = (blockIdx.x * blockDim.x + threadIdx.x) >> 5;
    int lane = threadIdx.x & 31;
    if (warp >= NN) return;
    int d = g_deg[warp];
    int o = g_off[warp];
    float a0 = 0.f, a1 = 0.f;
    int t = 0;
    for (; t + 2 <= d; t += 2) {
        int nb0 = g_adj[o + t];
        int nb1 = g_adj[o + t + 1];
        a0 += feat[nb0 * D + lane];
        a1 += feat[nb0 * D + 32 + lane];
        a0 += feat[nb1 * D + lane];
        a1 += feat[nb1 * D + 32 + lane];
    }
    if (t < d) {
        int nb = g_adj[o + t];
        a0 += feat[nb * D + lane];
        a1 += feat[nb * D + 32 + lane];
    }
    float inv = 1.0f / (float)max(d, 1);
    outm[warp * D + lane]      = a0 * inv;
    outm[warp * D + 32 + lane] = a1 * inv;
}

// ---------------- fused GEMM: out = [mean|x] @ [Wl^T;Wr^T] + b (+relu) ------
#define AS_STRIDE 129
#define BS_STRIDE 65
#define GEMM_SMEM ((128 * AS_STRIDE + 128 * BS_STRIDE + 64) * 4)

__global__ __launch_bounds__(128) void k_gemm(
    const float* __restrict__ meanp, const float* __restrict__ xp,
    const float* __restrict__ Wl, const float* __restrict__ Wr,
    const float* __restrict__ bias, float* __restrict__ outp, int do_relu)
{
    extern __shared__ float sm[];
    float* As = sm;                     // [k][m] stride 129
    float* Bs = sm + 128 * AS_STRIDE;   // [k][j] stride 65
    float* bs = Bs + 128 * BS_STRIDE;   // [64]
    float* Cs = As;                     // aliased after compute

    int tid   = threadIdx.x;
    int node0 = blockIdx.x * 128;

    // B = [Wl^T ; Wr^T]
    for (int idx = tid; idx < 4096; idx += 128) {
        int j = idx >> 6, k = idx & 63;
        Bs[k * BS_STRIDE + j]        = Wl[idx];
        Bs[(k + 64) * BS_STRIDE + j] = Wr[idx];
    }
    if (tid < 64) bs[tid] = bias[tid];

    // A-tile transposed: As[k][m] = (k<64 ? mean[m][k] : x[m][k-64])
    for (int idx = tid; idx < 128 * 128; idx += 128) {
        int m = idx >> 7, k = idx & 127;
        float v = 0.f;
        int node = node0 + m;
        if (node < NN)
            v = (k < 64) ? meanp[node * D + k] : xp[node * D + (k - 64)];
        As[k * AS_STRIDE + m] = v;
    }
    __syncthreads();

    int mi = tid & 15;
    int ji = tid >> 4;

    float acc[8][8];
#pragma unroll
    for (int i = 0; i < 8; i++)
#pragma unroll
        for (int j = 0; j < 8; j++) acc[i][j] = 0.f;

#pragma unroll 4
    for (int k = 0; k < 128; k++) {
        float a[8], b[8];
#pragma unroll
        for (int i = 0; i < 8; i++) a[i] = As[k * AS_STRIDE + mi + 16 * i];
#pragma unroll
        for (int j = 0; j < 8; j++) b[j] = Bs[k * BS_STRIDE + ji + 8 * j];
#pragma unroll
        for (int i = 0; i < 8; i++)
#pragma unroll
            for (int j = 0; j < 8; j++) acc[i][j] = fmaf(a[i], b[j], acc[i][j]);
    }
    __syncthreads();

#pragma unroll
    for (int i = 0; i < 8; i++)
#pragma unroll
        for (int j = 0; j < 8; j++)
            Cs[(mi + 16 * i) * BS_STRIDE + (ji + 8 * j)] = acc[i][j];
    __syncthreads();

    for (int idx = tid; idx < 128 * 64; idx += 128) {
        int m = idx >> 6, j = idx & 63;
        int node = node0 + m;
        if (node < NN) {
            float v = Cs[m * BS_STRIDE + j] + bs[j];
            if (do_relu) v = fmaxf(v, 0.f);
            outp[node * D + j] = v;
        }
    }
}

// ---------------- launch -----------------------------------------------------
extern "C" void kernel_launch(void* const* d_in, const int* in_sizes, int n_in,
                              void* d_out, int out_size)
{
    const float* x   = (const float*)d_in[0];
    const void*  ei  = d_in[1];
    const float* W1l = (const float*)d_in[2];
    const float* b1l = (const float*)d_in[3];
    const float* W1r = (const float*)d_in[4];
    const float* W2l = (const float*)d_in[5];
    const float* b2l = (const float*)d_in[6];
    const float* W2r = (const float*)d_in[7];
    float* out = (float*)d_out;

    cudaFuncSetAttribute(k_gemm, cudaFuncAttributeMaxDynamicSharedMemorySize, GEMM_SMEM);

    float* d_mean; cudaGetSymbolAddress((void**)&d_mean, g_mean);
    float* d_h;    cudaGetSymbolAddress((void**)&d_h,    g_h);

    // dtype probe + CSR build (rebuilt every call: determinism rule)
    k_detect<<<1, 256>>>((const long long*)ei);
    k_zero  <<<(NN + 255) / 256, 256>>>();
    k_hist  <<<(NE + 255) / 256, 256>>>(ei);
    k_scan1 <<<SCAN_NB, SCAN_B>>>();
    k_scan2 <<<1, 32>>>();
    k_scan3 <<<SCAN_NB, SCAN_B>>>();
    k_fill  <<<(NE + 255) / 256, 256>>>(ei);

    int agg_grid  = (NN * 32 + 255) / 256;     // warp per node
    int gemm_grid = (NN + 127) / 128;

    // Layer 1
    k_agg <<<agg_grid, 256>>>(x, d_mean);
    k_gemm<<<gemm_grid, 128, GEMM_SMEM>>>(d_mean, x, W1l, W1r, b1l, d_h, 1);
    // Layer 2
    k_agg <<<agg_grid, 256>>>(d_h, d_mean);
    k_gemm<<<gemm_grid, 128, GEMM_SMEM>>>(d_mean, d_h, W2l, W2r, b2l, out, 0);
}

// round 4
// speedup vs baseline: 2.9680x; 2.9680x over previous
#include <cuda_runtime.h>
#include <cuda_bf16.h>
#include <math.h>
#include <stdint.h>

#define NN 100000
#define NE 1000000
#define D  64

// ---------------- scratch ----------------------------------------------------
__device__ int   g_deg[NN];
__device__ int   g_cur[NN];
__device__ int   g_off[NN];
__device__ int   g_adj[NE];
__device__ float g_mean[NN * D];
__device__ float g_h[NN * D];
__device__ int   g_bsum[128];
__device__ int   g_boff[128];
__device__ int   g_is64;

#define SCAN_B 1024
#define SCAN_NB ((NN + SCAN_B - 1) / SCAN_B)   // 98

// ---------------- edge dtype handling ---------------------------------------
__device__ __forceinline__ int edge_at(const void* ei, int idx) {
    if (g_is64) return (int)((const long long*)ei)[idx];
    return ((const int*)ei)[idx];
}

// init: zero counters everywhere; last block also runs the dtype probe.
__global__ void k_init(const long long* __restrict__ ei) {
    int i = blockIdx.x * blockDim.x + threadIdx.x;
    if (i < NN) { g_deg[i] = 0; g_cur[i] = 0; }
    if (blockIdx.x == gridDim.x - 1) {
        __shared__ int bad;
        if (threadIdx.x == 0) bad = 0;
        __syncthreads();
        for (int t = threadIdx.x; t < 2048; t += blockDim.x) {
            long long v = ei[t];
            if (v < 0 || v >= NN) bad = 1;
        }
        __syncthreads();
        if (threadIdx.x == 0) g_is64 = bad ? 0 : 1;
    }
}

// ---------------- CSR build --------------------------------------------------
__global__ void k_hist(const void* __restrict__ ei) {
    int e = blockIdx.x * blockDim.x + threadIdx.x;
    if (e < NE) {
        int dst = edge_at(ei, NE + e);
        if ((unsigned)dst < NN) atomicAdd(&g_deg[dst], 1);
    }
}

__global__ void k_scan1(void) {
    __shared__ int wsum[32];
    int i = blockIdx.x * SCAN_B + threadIdx.x;
    int lane = threadIdx.x & 31, w = threadIdx.x >> 5;
    int v = (i < NN) ? g_deg[i] : 0;
    int p = v;
#pragma unroll
    for (int st = 1; st < 32; st <<= 1) {
        int t = __shfl_up_sync(0xFFFFFFFFu, p, st);
        if (lane >= st) p += t;
    }
    if (lane == 31) wsum[w] = p;
    __syncthreads();
    if (w == 0) {
        int s = wsum[lane];
#pragma unroll
        for (int st = 1; st < 32; st <<= 1) {
            int t = __shfl_up_sync(0xFFFFFFFFu, s, st);
            if (lane >= st) s += t;
        }
        wsum[lane] = s;
    }
    __syncthreads();
    int base = (w > 0) ? wsum[w - 1] : 0;
    if (i < NN) g_off[i] = base + p - v;       // exclusive within chunk
    if (threadIdx.x == SCAN_B - 1) g_bsum[blockIdx.x] = base + p;
}

__global__ void k_scan2(void) {
    if (threadIdx.x == 0) {
        int acc = 0;
        for (int b = 0; b < SCAN_NB; b++) {
            int t = g_bsum[b];
            g_boff[b] = acc;
            acc += t;
        }
    }
}

__global__ void k_scan3(void) {
    int i = blockIdx.x * SCAN_B + threadIdx.x;
    if (i < NN) g_off[i] += g_boff[blockIdx.x];
}

__global__ void k_fill(const void* __restrict__ ei) {
    int e = blockIdx.x * blockDim.x + threadIdx.x;
    if (e < NE) {
        int src = edge_at(ei, e);
        int dst = edge_at(ei, NE + e);
        if ((unsigned)dst < NN && (unsigned)src < NN) {
            int p = g_off[dst] + atomicAdd(&g_cur[dst], 1);
            g_adj[p] = src;
        }
    }
}

// ---------------- mean aggregation: half-warp per node, float4 --------------
__global__ void k_agg(const float* __restrict__ feat, float* __restrict__ outm) {
    int hw = (blockIdx.x * blockDim.x + threadIdx.x) >> 4;  // node id
    int c  = threadIdx.x & 15;                              // float4 lane
    if (hw >= NN) return;
    int d = g_deg[hw];
    int o = g_off[hw];
    const float4* f4 = (const float4*)feat;
    float4 a = make_float4(0.f, 0.f, 0.f, 0.f);
    int t = 0;
    for (; t + 4 <= d; t += 4) {
        int nb0 = g_adj[o + t];
        int nb1 = g_adj[o + t + 1];
        int nb2 = g_adj[o + t + 2];
        int nb3 = g_adj[o + t + 3];
        float4 v0 = f4[nb0 * 16 + c];
        float4 v1 = f4[nb1 * 16 + c];
        float4 v2 = f4[nb2 * 16 + c];
        float4 v3 = f4[nb3 * 16 + c];
        a.x += v0.x + v1.x + v2.x + v3.x;
        a.y += v0.y + v1.y + v2.y + v3.y;
        a.z += v0.z + v1.z + v2.z + v3.z;
        a.w += v0.w + v1.w + v2.w + v3.w;
    }
    for (; t < d; t++) {
        int nb = g_adj[o + t];
        float4 v = f4[nb * 16 + c];
        a.x += v.x; a.y += v.y; a.z += v.z; a.w += v.w;
    }
    float inv = 1.0f / (float)max(d, 1);
    a.x *= inv; a.y *= inv; a.z *= inv; a.w *= inv;
    ((float4*)outm)[hw * 16 + c] = a;
}

// ---------------- HMMA bf16 3-pass GEMM --------------------------------------
// out[128,64] = [mean|x][128,128] @ B[128,64] + bias (+relu),
// B[k][j] = (k<64 ? Wl[j][k] : Wr[j][k-64]).
// fp32 -> (hi,lo) bf16 split; acc += Ah*Bh + Ah*Bl + Al*Bh  (fp32 accum).
// mma.sync.m16n8k16 row.col: A[m][k] from smem rows, B frag = W rows (k-contig).
#define ASTRIDE_W 68            // words per A/B smem row (136 bf16: 128 + 8 pad)
#define OFF_BIAS 0
#define OFF_AHI  256
#define OFF_ALO  (OFF_AHI + 128 * ASTRIDE_W * 4)    // +34816
#define OFF_BHI  (OFF_ALO + 128 * ASTRIDE_W * 4)
#define OFF_BLO  (OFF_BHI + 64 * ASTRIDE_W * 4)     // +17408
#define GEMM_SMEM (OFF_BLO + 64 * ASTRIDE_W * 4)    // 104704 B

__device__ __forceinline__ void hilo_pack(float4 v, uint32_t& h01, uint32_t& h23,
                                          uint32_t& l01, uint32_t& l23) {
    uint32_t u0 = __float_as_uint(v.x), u1 = __float_as_uint(v.y);
    uint32_t u2 = __float_as_uint(v.z), u3 = __float_as_uint(v.w);
    float h0 = __uint_as_float(u0 & 0xFFFF0000u);
    float h1 = __uint_as_float(u1 & 0xFFFF0000u);
    float h2 = __uint_as_float(u2 & 0xFFFF0000u);
    float h3 = __uint_as_float(u3 & 0xFFFF0000u);
    h01 = (u0 >> 16) | (u1 & 0xFFFF0000u);
    h23 = (u2 >> 16) | (u3 & 0xFFFF0000u);
    float l0 = v.x - h0, l1 = v.y - h1, l2 = v.z - h2, l3 = v.w - h3;
    asm("cvt.rn.bf16x2.f32 %0, %1, %2;" : "=r"(l01) : "f"(l1), "f"(l0));
    asm("cvt.rn.bf16x2.f32 %0, %1, %2;" : "=r"(l23) : "f"(l3), "f"(l2));
}

__device__ __forceinline__ void mma16816(float* d, uint32_t a0, uint32_t a1,
                                         uint32_t a2, uint32_t a3,
                                         uint32_t b0, uint32_t b1) {
    asm volatile(
        "mma.sync.aligned.m16n8k16.row.col.f32.bf16.bf16.f32 "
        "{%0,%1,%2,%3}, {%4,%5,%6,%7}, {%8,%9}, {%0,%1,%2,%3};"
        : "+f"(d[0]), "+f"(d[1]), "+f"(d[2]), "+f"(d[3])
        : "r"(a0), "r"(a1), "r"(a2), "r"(a3), "r"(b0), "r"(b1));
}

__global__ __launch_bounds__(128) void k_gemm_mma(
    const float* __restrict__ meanp, const float* __restrict__ xp,
    const float* __restrict__ Wl, const float* __restrict__ Wr,
    const float* __restrict__ bias, float* __restrict__ outp, int do_relu)
{
    extern __shared__ char smc[];
    int tid = threadIdx.x;
    int wid = tid >> 5, lane = tid & 31;
    int node0 = blockIdx.x * 128;

    if (tid < 64) *(float*)(smc + OFF_BIAS + tid * 4) = bias[tid];

    uint2* Ah = (uint2*)(smc + OFF_AHI);
    uint2* Al = (uint2*)(smc + OFF_ALO);
    uint2* Bh = (uint2*)(smc + OFF_BHI);
    uint2* Bl = (uint2*)(smc + OFF_BLO);

    // ---- stage A: 128 rows x 128 k (float4 per thread-iter) ----
    {
        int k4 = tid & 31;          // k = k4*4 .. +3
        int ms = tid >> 5;          // 0..3
        int kk = k4 * 4;
        const float* basep = (kk < 64) ? (meanp + kk) : (xp + kk - 64);
#pragma unroll 4
        for (int m = ms; m < 128; m += 4) {
            int node = node0 + m;
            float4 v = make_float4(0.f, 0.f, 0.f, 0.f);
            if (node < NN) v = *(const float4*)(basep + node * D);
            uint32_t h01, h23, l01, l23;
            hilo_pack(v, h01, h23, l01, l23);
            int w2 = (m * ASTRIDE_W + (kk >> 1)) >> 1;   // uint2 index
            Ah[w2] = make_uint2(h01, h23);
            Al[w2] = make_uint2(l01, l23);
        }
    }
    // ---- stage B: 64 rows x 128 k ----
    {
        int k4 = tid & 31;
        int js = tid >> 5;
        int kk = k4 * 4;
        const float* basep = (kk < 64) ? (Wl + kk) : (Wr + kk - 64);
#pragma unroll 4
        for (int j = js; j < 64; j += 4) {
            float4 v = *(const float4*)(basep + j * 64);
            uint32_t h01, h23, l01, l23;
            hilo_pack(v, h01, h23, l01, l23);
            int w2 = (j * ASTRIDE_W + (kk >> 1)) >> 1;
            Bh[w2] = make_uint2(h01, h23);
            Bl[w2] = make_uint2(l01, l23);
        }
    }
    __syncthreads();

    // ---- main loop: warp computes rows [wid*32, wid*32+32) x 64 cols ----
    const uint32_t* AhW = (const uint32_t*)(smc + OFF_AHI);
    const uint32_t* AlW = (const uint32_t*)(smc + OFF_ALO);
    const uint32_t* BhW = (const uint32_t*)(smc + OFF_BHI);
    const uint32_t* BlW = (const uint32_t*)(smc + OFF_BLO);

    float acc[2][8][4];
#pragma unroll
    for (int mt = 0; mt < 2; mt++)
#pragma unroll
        for (int nt = 0; nt < 8; nt++)
#pragma unroll
            for (int r = 0; r < 4; r++) acc[mt][nt][r] = 0.f;

    int r4 = lane >> 2;        // 0..7
    int c4 = lane & 3;         // 0..3

#pragma unroll
    for (int ks = 0; ks < 8; ks++) {
        int kw = ks * 8 + c4;  // word offset along k (k = ks*16 + 2*c4)

        uint32_t bh[8][2], bl[8][2];
#pragma unroll
        for (int nt = 0; nt < 8; nt++) {
            int row = nt * 8 + r4;
            bh[nt][0] = BhW[row * ASTRIDE_W + kw];
            bh[nt][1] = BhW[row * ASTRIDE_W + kw + 4];
            bl[nt][0] = BlW[row * ASTRIDE_W + kw];
            bl[nt][1] = BlW[row * ASTRIDE_W + kw + 4];
        }
#pragma unroll
        for (int mt = 0; mt < 2; mt++) {
            int row = wid * 32 + mt * 16 + r4;
            uint32_t ah0 = AhW[row * ASTRIDE_W + kw];
            uint32_t ah2 = AhW[row * ASTRIDE_W + kw + 4];
            uint32_t ah1 = AhW[(row + 8) * ASTRIDE_W + kw];
            uint32_t ah3 = AhW[(row + 8) * ASTRIDE_W + kw + 4];
            uint32_t al0 = AlW[row * ASTRIDE_W + kw];
            uint32_t al2 = AlW[row * ASTRIDE_W + kw + 4];
            uint32_t al1 = AlW[(row + 8) * ASTRIDE_W + kw];
            uint32_t al3 = AlW[(row + 8) * ASTRIDE_W + kw + 4];
#pragma unroll
            for (int nt = 0; nt < 8; nt++) {
                mma16816(acc[mt][nt], ah0, ah1, ah2, ah3, bh[nt][0], bh[nt][1]);
                mma16816(acc[mt][nt], ah0, ah1, ah2, ah3, bl[nt][0], bl[nt][1]);
                mma16816(acc[mt][nt], al0, al1, al2, al3, bh[nt][0], bh[nt][1]);
            }
        }
    }

    // ---- epilogue: direct float2 stores ----
    const float* bsm = (const float*)(smc + OFF_BIAS);
#pragma unroll
    for (int mt = 0; mt < 2; mt++) {
        int row0 = node0 + wid * 32 + mt * 16 + r4;
#pragma unroll
        for (int nt = 0; nt < 8; nt++) {
            int col = nt * 8 + 2 * c4;
            float bx = bsm[col], by = bsm[col + 1];
            float f0 = acc[mt][nt][0] + bx, f1 = acc[mt][nt][1] + by;
            float f2 = acc[mt][nt][2] + bx, f3 = acc[mt][nt][3] + by;
            if (do_relu) {
                f0 = fmaxf(f0, 0.f); f1 = fmaxf(f1, 0.f);
                f2 = fmaxf(f2, 0.f); f3 = fmaxf(f3, 0.f);
            }
            if (row0 < NN)     *(float2*)(outp + row0 * D + col)       = make_float2(f0, f1);
            if (row0 + 8 < NN) *(float2*)(outp + (row0 + 8) * D + col) = make_float2(f2, f3);
        }
    }
}

// ---------------- launch -----------------------------------------------------
extern "C" void kernel_launch(void* const* d_in, const int* in_sizes, int n_in,
                              void* d_out, int out_size)
{
    const float* x   = (const float*)d_in[0];
    const void*  ei  = d_in[1];
    const float* W1l = (const float*)d_in[2];
    const float* b1l = (const float*)d_in[3];
    const float* W1r = (const float*)d_in[4];
    const float* W2l = (const float*)d_in[5];
    const float* b2l = (const float*)d_in[6];
    const float* W2r = (const float*)d_in[7];
    float* out = (float*)d_out;

    cudaFuncSetAttribute(k_gemm_mma, cudaFuncAttributeMaxDynamicSharedMemorySize, GEMM_SMEM);

    float* d_mean; cudaGetSymbolAddress((void**)&d_mean, g_mean);
    float* d_h;    cudaGetSymbolAddress((void**)&d_h,    g_h);

    k_init <<<(NN + 255) / 256, 256>>>((const long long*)ei);
    k_hist <<<(NE + 255) / 256, 256>>>(ei);
    k_scan1<<<SCAN_NB, SCAN_B>>>();
    k_scan2<<<1, 32>>>();
    k_scan3<<<SCAN_NB, SCAN_B>>>();
    k_fill <<<(NE + 255) / 256, 256>>>(ei);

    int agg_grid  = (NN * 16 + 255) / 256;   // half-warp per node
    int gemm_grid = (NN + 127) / 128;        // 782

    k_agg     <<<agg_grid, 256>>>(x, d_mean);
    k_gemm_mma<<<gemm_grid, 128, GEMM_SMEM>>>(d_mean, x, W1l, W1r, b1l, d_h, 1);
    k_agg     <<<agg_grid, 256>>>(d_h, d_mean);
    k_gemm_mma<<<gemm_grid, 128, GEMM_SMEM>>>(d_mean, d_h, W2l, W2r, b2l, out, 0);
}